// round 5
// baseline (speedup 1.0000x reference)
#include <cuda_runtime.h>

// DynamicPooling, fused online-softmax + L2-resident batch groups (R5).
// B=64, N=4096, D=256, fp32. x: [B,N,D], m: [B,N,1]. Out: w [B,N], s [B,D].
//
// R5 vs R4: evict_last requires 256-bit loads on sm_103 -> each lane loads
// its 32-byte row slice with one ld.global.nc.L2::evict_last.v4.b64
// (lane l owns columns 8l..8l+7; one warp-load = one full row).

namespace {
constexpr int Bb = 64;
constexpr int Nn = 4096;
constexpr int Dd = 256;
constexpr int NCHUNK = 32;            // N-chunks per batch
constexpr int ROWS = Nn / NCHUNK;     // 128 rows per block
constexpr int WARPS = 8;
constexpr int RPW = ROWS / WARPS;     // 16 rows per warp
constexpr int GRP = 16;               // batches per L2-resident group
}

__device__ float g_part[Bb * NCHUNK * Dd];  // unnormalized sigma partials [b][c][d]
__device__ float g_M[Bb * NCHUNK];          // per-chunk local max  [b][c]
__device__ float g_Z[Bb * NCHUNK];          // per-chunk local mass [b][c]
__device__ float g_b[Bb * Nn];

// 32-byte x load with L2 evict_last priority (read-only path).
__device__ __forceinline__ void ldg_el8(const float* p, float4& A, float4& B) {
    asm volatile(
        "{\n\t"
        ".reg .b64 q0,q1,q2,q3;\n\t"
        "ld.global.nc.L2::evict_last.v4.b64 {q0,q1,q2,q3}, [%8];\n\t"
        "mov.b64 {%0,%1}, q0;\n\t"
        "mov.b64 {%2,%3}, q1;\n\t"
        "mov.b64 {%4,%5}, q2;\n\t"
        "mov.b64 {%6,%7}, q3;\n\t"
        "}"
        : "=f"(A.x), "=f"(A.y), "=f"(A.z), "=f"(A.w),
          "=f"(B.x), "=f"(B.y), "=f"(B.z), "=f"(B.w)
        : "l"(p));
}

// MODE 0: sigma only (uniform weights). MODE 1: head-combine -> s; b-update;
// next-sigma partials. MODE 2: head-combine -> s (write out_s); b-update only.
// ZEROB: incoming b treated as 0.
template <int MODE, bool ZEROB>
__global__ void __launch_bounds__(256) fused_sweep_kernel(
    const float* __restrict__ x, const float* __restrict__ m,
    int b0, float* __restrict__ out_s) {
    const int b = b0 + blockIdx.y;
    const int c = blockIdx.x;
    const int t = threadIdx.x, w = t >> 5, l = t & 31;
    const int n0 = c * ROWS;

    __shared__ float s_sh[Dd];
    __shared__ float m_sh[ROWS];
    __shared__ float b_sh[ROWS];
    __shared__ float sm_acc[WARPS * Dd];
    __shared__ float sm_M[WARPS], sm_Z[WARPS];
    __shared__ float sm_es[WARPS];
    __shared__ float red[256];
    __shared__ float hm[NCHUNK], hz[NCHUNK], hes[NCHUNK];

    if (t < ROWS) {
        int gi = b * Nn + n0 + t;
        m_sh[t] = m[gi];
        if (MODE != 0) b_sh[t] = ZEROB ? 0.0f : g_b[gi];
    }

    if (MODE != 0) {
        // head-combine: rebuild s from previous sweep's partials.
        if (t < NCHUNK) {
            hm[t] = g_M[b * NCHUNK + t];
            hz[t] = g_Z[b * NCHUNK + t];
        }
        __syncthreads();
        float Mg = hm[0];
#pragma unroll
        for (int k = 1; k < NCHUNK; k++) Mg = fmaxf(Mg, hm[k]);
        if (t < NCHUNK) hes[t] = __expf(hm[t] - Mg);   // exp hoisted
        __syncthreads();

        float v = 0.0f, Zg = 0.0f;
#pragma unroll
        for (int k = 0; k < NCHUNK; k++) {
            v = fmaf(hes[k], g_part[((size_t)b * NCHUNK + k) * Dd + t], v);
            Zg = fmaf(hes[k], hz[k], Zg);
        }
        const float sigma = v / Zg;
        red[t] = sigma * sigma;
        __syncthreads();
#pragma unroll
        for (int s = 128; s > 0; s >>= 1) {
            if (t < s) red[t] += red[t + s];
            __syncthreads();
        }
        const float n2 = red[0];
        const float norm = sqrtf(n2);
        const float sv = (n2 / (1.0f + n2) / (norm + 1e-8f)) * sigma;
        s_sh[t] = sv;
        if (MODE == 2 && c == 0 && out_s) out_s[b * Dd + t] = sv;
    }
    __syncthreads();

    const float* xb = x + ((size_t)b * Nn + n0) * Dd;
    const int r0 = w * RPW;
    const int d0 = l << 3;  // lane owns columns d0..d0+7

    // prefetch depth 2 (one 32B load per row per lane)
    float4 p0a, p0b, p1a, p1b;
    ldg_el8(xb + (size_t)r0 * Dd + d0, p0a, p0b);
    ldg_el8(xb + (size_t)(r0 + 1) * Dd + d0, p1a, p1b);

    float acc[8] = {0, 0, 0, 0, 0, 0, 0, 0};
    float M = (MODE == 0) ? 0.0f : -1e30f;
    float Z = 0.0f;

#pragma unroll 4
    for (int i = 0; i < RPW; i++) {
        const int n = r0 + i;
        float4 a0 = p0a, a1 = p0b;
        p0a = p1a; p0b = p1b;
        if (i + 2 < RPW)
            ldg_el8(xb + (size_t)(n + 2) * Dd + d0, p1a, p1b);
        const float mn = m_sh[n];

        if (MODE == 0) {
            acc[0] = fmaf(mn, a0.x, acc[0]);
            acc[1] = fmaf(mn, a0.y, acc[1]);
            acc[2] = fmaf(mn, a0.z, acc[2]);
            acc[3] = fmaf(mn, a0.w, acc[3]);
            acc[4] = fmaf(mn, a1.x, acc[4]);
            acc[5] = fmaf(mn, a1.y, acc[5]);
            acc[6] = fmaf(mn, a1.z, acc[6]);
            acc[7] = fmaf(mn, a1.w, acc[7]);
            Z += 1.0f;
        } else {
            float dot = a0.x * s_sh[d0]     + a0.y * s_sh[d0 + 1] +
                        a0.z * s_sh[d0 + 2] + a0.w * s_sh[d0 + 3] +
                        a1.x * s_sh[d0 + 4] + a1.y * s_sh[d0 + 5] +
                        a1.z * s_sh[d0 + 6] + a1.w * s_sh[d0 + 7];
#pragma unroll
            for (int o = 16; o > 0; o >>= 1)
                dot += __shfl_xor_sync(0xffffffffu, dot, o);

            const float bnew = fmaf(mn, dot, b_sh[n]);
            if (l == 0) g_b[b * Nn + n0 + n] = bnew;

            if (MODE == 1) {
                const float logit = mn * bnew;
                const float Mn = fmaxf(M, logit);
                const float scale = __expf(M - Mn);
                const float e = __expf(logit - Mn);
                Z = fmaf(Z, scale, e);
                const float wv = e * mn;
                acc[0] = fmaf(wv, a0.x, acc[0] * scale);
                acc[1] = fmaf(wv, a0.y, acc[1] * scale);
                acc[2] = fmaf(wv, a0.z, acc[2] * scale);
                acc[3] = fmaf(wv, a0.w, acc[3] * scale);
                acc[4] = fmaf(wv, a1.x, acc[4] * scale);
                acc[5] = fmaf(wv, a1.y, acc[5] * scale);
                acc[6] = fmaf(wv, a1.z, acc[6] * scale);
                acc[7] = fmaf(wv, a1.w, acc[7] * scale);
                M = Mn;
            }
        }
    }

    if (MODE != 2) {
        *reinterpret_cast<float4*>(&sm_acc[w * Dd + d0]) =
            make_float4(acc[0], acc[1], acc[2], acc[3]);
        *reinterpret_cast<float4*>(&sm_acc[w * Dd + d0 + 4]) =
            make_float4(acc[4], acc[5], acc[6], acc[7]);
        if (l == 0) { sm_M[w] = M; sm_Z[w] = Z; }
        __syncthreads();

        float Mb = sm_M[0];
#pragma unroll
        for (int k = 1; k < WARPS; k++) Mb = fmaxf(Mb, sm_M[k]);
        if (t < WARPS) sm_es[t] = __expf(sm_M[t] - Mb);  // exp hoisted
        __syncthreads();

        float sig = 0.0f;
#pragma unroll
        for (int k = 0; k < WARPS; k++)
            sig = fmaf(sm_es[k], sm_acc[k * Dd + t], sig);
        g_part[((size_t)b * NCHUNK + c) * Dd + t] = sig;
        if (t == 0) {
            float Zb = 0.0f;
#pragma unroll
            for (int k = 0; k < WARPS; k++)
                Zb = fmaf(sm_es[k], sm_Z[k], Zb);
            g_M[b * NCHUNK + c] = Mb;
            g_Z[b * NCHUNK + c] = Zb;
        }
    }
}

// Final w = softmax(b) over N (no m factor). Exact 2-pass in-register.
__global__ void __launch_bounds__(256) final_softmax_kernel(float* __restrict__ out_w) {
    const int b = blockIdx.x, t = threadIdx.x;
    const float* bb = g_b + (size_t)b * Nn;

    float vals[16];
    float lmax = -3.4e38f;
#pragma unroll
    for (int i = 0; i < 16; i++) {
        vals[i] = bb[t + i * 256];
        lmax = fmaxf(lmax, vals[i]);
    }
    __shared__ float red[256];
    red[t] = lmax;
    __syncthreads();
#pragma unroll
    for (int s = 128; s > 0; s >>= 1) {
        if (t < s) red[t] = fmaxf(red[t], red[t + s]);
        __syncthreads();
    }
    const float gmax = red[0];
    __syncthreads();

    float lsum = 0.0f;
#pragma unroll
    for (int i = 0; i < 16; i++) {
        vals[i] = __expf(vals[i] - gmax);
        lsum += vals[i];
    }
    red[t] = lsum;
    __syncthreads();
#pragma unroll
    for (int s = 128; s > 0; s >>= 1) {
        if (t < s) red[t] += red[t + s];
        __syncthreads();
    }
    const float inv = 1.0f / red[0];
#pragma unroll
    for (int i = 0; i < 16; i++)
        out_w[(size_t)b * Nn + t + i * 256] = vals[i] * inv;
}

extern "C" void kernel_launch(void* const* d_in, const int* in_sizes, int n_in,
                              void* d_out, int out_size) {
    (void)in_sizes; (void)n_in; (void)out_size;
    const float* x = (const float*)d_in[0];
    const float* m = (const float*)d_in[1];
    float* out = (float*)d_out;
    float* out_w = out;             // [B, N]
    float* out_s = out + Bb * Nn;   // [B, D]

    const dim3 grid(NCHUNK, GRP);

    for (int g = 0; g < Bb / GRP; ++g) {
        const int b0 = g * GRP;
        fused_sweep_kernel<0, false><<<grid, 256>>>(x, m, b0, nullptr); // sigma1
        fused_sweep_kernel<1, true><<<grid, 256>>>(x, m, b0, nullptr);  // b1+sigma2
        fused_sweep_kernel<1, false><<<grid, 256>>>(x, m, b0, nullptr); // b2+sigma3
        fused_sweep_kernel<2, false><<<grid, 256>>>(x, m, b0, out_s);   // s3+b3
    }
    final_softmax_kernel<<<Bb, 256>>>(out_w);  // w = softmax(b3)
}

// round 6
// speedup vs baseline: 1.1992x; 1.1992x over previous
#include <cuda_runtime.h>

// DynamicPooling R6: fused schedule, latency fixes.
// B=64, N=4096, D=256, fp32. x: [B,N,D], m: [B,N,1]. Out: w [B,N], s [B,D].
//
// vs R3/R5:
//  - plain float4 loads (2 per row), rolling prefetch depth 3 (6 loads in
//    flight per lane) -> enough MLP to saturate DRAM
//  - NO online-max in the softmax accumulation: |logit| <= 24 is safe in
//    fp32 (|squash| <= 0.5), removing the serial per-row rescale chain
//  - __launch_bounds__(256,4): 4 blocks/SM so grid-512 launches are 1 wave

namespace {
constexpr int Bb = 64;
constexpr int Nn = 4096;
constexpr int Dd = 256;
constexpr int NCHUNK = 32;            // N-chunks per batch
constexpr int ROWS = Nn / NCHUNK;     // 128 rows per block
constexpr int WARPS = 8;
constexpr int RPW = ROWS / WARPS;     // 16 rows per warp
constexpr int GRP = 16;               // batches per group
constexpr int PF = 3;                 // prefetch depth (rows)
}

__device__ float g_part[Bb * NCHUNK * Dd];  // unnormalized sigma partials [b][c][d]
__device__ float g_Z[Bb * NCHUNK];          // per-chunk mass [b][c]
__device__ float g_b[Bb * Nn];

// MODE 0: sigma only (uniform weights). MODE 1: head-combine -> s; b-update;
// next-sigma partials. MODE 2: head-combine -> s (write out_s); b-update only.
// ZEROB: incoming b treated as 0.
template <int MODE, bool ZEROB>
__global__ void __launch_bounds__(256, 4) fused_sweep_kernel(
    const float* x, const float* __restrict__ m,
    int b0, float* __restrict__ out_s) {
    const int b = b0 + blockIdx.y;
    const int c = blockIdx.x;
    const int t = threadIdx.x, w = t >> 5, l = t & 31;
    const int n0 = c * ROWS;

    __shared__ float s_sh[Dd];
    __shared__ float m_sh[ROWS];
    __shared__ float b_sh[ROWS];
    __shared__ float sm_acc[WARPS * Dd];
    __shared__ float sm_Z[WARPS];
    __shared__ float red[256];
    __shared__ float hz[NCHUNK];

    if (t < ROWS) {
        int gi = b * Nn + n0 + t;
        m_sh[t] = m[gi];
        if (MODE != 0) b_sh[t] = ZEROB ? 0.0f : g_b[gi];
    }

    if (MODE != 0) {
        // head-combine: rebuild s from previous sweep's partials (no exps:
        // weights were raw exp(m*b), so just sum partials / sum masses).
        if (t < NCHUNK) hz[t] = g_Z[b * NCHUNK + t];
        __syncthreads();
        float v = 0.0f, Zg = 0.0f;
#pragma unroll
        for (int k = 0; k < NCHUNK; k++) {
            v += g_part[((size_t)b * NCHUNK + k) * Dd + t];
            Zg += hz[k];
        }
        const float sigma = v / Zg;
        red[t] = sigma * sigma;
        __syncthreads();
#pragma unroll
        for (int s = 128; s > 0; s >>= 1) {
            if (t < s) red[t] += red[t + s];
            __syncthreads();
        }
        const float n2 = red[0];
        const float norm = sqrtf(n2);
        const float sv = (n2 / (1.0f + n2) / (norm + 1e-8f)) * sigma;
        s_sh[t] = sv;
        if (MODE == 2 && c == 0 && out_s) out_s[b * Dd + t] = sv;
    }
    __syncthreads();

    const float* xb = x + ((size_t)b * Nn + n0) * Dd;
    const int r0 = w * RPW;
    const int d0 = l << 2;

    // rolling prefetch, depth PF rows (2 float4 per row per lane)
    float4 pa[PF], pb[PF];
#pragma unroll
    for (int j = 0; j < PF; j++) {
        const float* xr = xb + (size_t)(r0 + j) * Dd;
        pa[j] = *reinterpret_cast<const float4*>(xr + d0);
        pb[j] = *reinterpret_cast<const float4*>(xr + 128 + d0);
    }

    float acc[8] = {0, 0, 0, 0, 0, 0, 0, 0};
    float Z = 0.0f;

#pragma unroll
    for (int i = 0; i < RPW; i++) {
        const int n = r0 + i;
        const float4 a0 = pa[i % PF];
        const float4 a1 = pb[i % PF];
        if (i + PF < RPW) {
            const float* xn = xb + (size_t)(n + PF) * Dd;
            pa[i % PF] = *reinterpret_cast<const float4*>(xn + d0);
            pb[i % PF] = *reinterpret_cast<const float4*>(xn + 128 + d0);
        }
        const float mn = m_sh[n];

        if (MODE == 0) {
            acc[0] = fmaf(mn, a0.x, acc[0]);
            acc[1] = fmaf(mn, a0.y, acc[1]);
            acc[2] = fmaf(mn, a0.z, acc[2]);
            acc[3] = fmaf(mn, a0.w, acc[3]);
            acc[4] = fmaf(mn, a1.x, acc[4]);
            acc[5] = fmaf(mn, a1.y, acc[5]);
            acc[6] = fmaf(mn, a1.z, acc[6]);
            acc[7] = fmaf(mn, a1.w, acc[7]);
            Z += 1.0f;
        } else {
            float dot = a0.x * s_sh[d0]       + a0.y * s_sh[d0 + 1] +
                        a0.z * s_sh[d0 + 2]   + a0.w * s_sh[d0 + 3] +
                        a1.x * s_sh[128 + d0] + a1.y * s_sh[129 + d0] +
                        a1.z * s_sh[130 + d0] + a1.w * s_sh[131 + d0];
#pragma unroll
            for (int o = 16; o > 0; o >>= 1)
                dot += __shfl_xor_sync(0xffffffffu, dot, o);

            const float bnew = fmaf(mn, dot, b_sh[n]);
            if (l == 0) g_b[b * Nn + n0 + n] = bnew;

            if (MODE == 1) {
                // raw exp weight, no max subtraction (|m*bnew| <= ~24, safe)
                const float e = __expf(mn * bnew);
                Z += e;
                const float wv = e * mn;
                acc[0] = fmaf(wv, a0.x, acc[0]);
                acc[1] = fmaf(wv, a0.y, acc[1]);
                acc[2] = fmaf(wv, a0.z, acc[2]);
                acc[3] = fmaf(wv, a0.w, acc[3]);
                acc[4] = fmaf(wv, a1.x, acc[4]);
                acc[5] = fmaf(wv, a1.y, acc[5]);
                acc[6] = fmaf(wv, a1.z, acc[6]);
                acc[7] = fmaf(wv, a1.w, acc[7]);
            }
        }
    }

    if (MODE != 2) {
        *reinterpret_cast<float4*>(&sm_acc[w * Dd + d0]) =
            make_float4(acc[0], acc[1], acc[2], acc[3]);
        *reinterpret_cast<float4*>(&sm_acc[w * Dd + 128 + d0]) =
            make_float4(acc[4], acc[5], acc[6], acc[7]);
        if (l == 0) sm_Z[w] = Z;
        __syncthreads();

        float sig = 0.0f;
#pragma unroll
        for (int k = 0; k < WARPS; k++)
            sig += sm_acc[k * Dd + t];
        g_part[((size_t)b * NCHUNK + c) * Dd + t] = sig;
        if (t == 0) {
            float Zb = 0.0f;
#pragma unroll
            for (int k = 0; k < WARPS; k++) Zb += sm_Z[k];
            g_Z[b * NCHUNK + c] = Zb;
        }
    }
}

// Final w = softmax(b) over N (no m factor). Exact 2-pass in-register.
__global__ void __launch_bounds__(256) final_softmax_kernel(float* __restrict__ out_w) {
    const int b = blockIdx.x, t = threadIdx.x;
    const float* bb = g_b + (size_t)b * Nn;

    float vals[16];
    float lmax = -3.4e38f;
#pragma unroll
    for (int i = 0; i < 16; i++) {
        vals[i] = bb[t + i * 256];
        lmax = fmaxf(lmax, vals[i]);
    }
    __shared__ float red[256];
    red[t] = lmax;
    __syncthreads();
#pragma unroll
    for (int s = 128; s > 0; s >>= 1) {
        if (t < s) red[t] = fmaxf(red[t], red[t + s]);
        __syncthreads();
    }
    const float gmax = red[0];
    __syncthreads();

    float lsum = 0.0f;
#pragma unroll
    for (int i = 0; i < 16; i++) {
        vals[i] = __expf(vals[i] - gmax);
        lsum += vals[i];
    }
    red[t] = lsum;
    __syncthreads();
#pragma unroll
    for (int s = 128; s > 0; s >>= 1) {
        if (t < s) red[t] += red[t + s];
        __syncthreads();
    }
    const float inv = 1.0f / red[0];
#pragma unroll
    for (int i = 0; i < 16; i++)
        out_w[(size_t)b * Nn + t + i * 256] = vals[i] * inv;
}

extern "C" void kernel_launch(void* const* d_in, const int* in_sizes, int n_in,
                              void* d_out, int out_size) {
    (void)in_sizes; (void)n_in; (void)out_size;
    const float* x = (const float*)d_in[0];
    const float* m = (const float*)d_in[1];
    float* out = (float*)d_out;
    float* out_w = out;             // [B, N]
    float* out_s = out + Bb * Nn;   // [B, D]

    const dim3 grid(NCHUNK, GRP);

    for (int g = 0; g < Bb / GRP; ++g) {
        const int b0 = g * GRP;
        fused_sweep_kernel<0, false><<<grid, 256>>>(x, m, b0, nullptr); // sigma1
        fused_sweep_kernel<1, true><<<grid, 256>>>(x, m, b0, nullptr);  // b1+sigma2
        fused_sweep_kernel<1, false><<<grid, 256>>>(x, m, b0, nullptr); // b2+sigma3
        fused_sweep_kernel<2, false><<<grid, 256>>>(x, m, b0, out_s);   // s3+b3
    }
    final_softmax_kernel<<<Bb, 256>>>(out_w);  // w = softmax(b3)
}